// round 7
// baseline (speedup 1.0000x reference)
#include <cuda_runtime.h>
#include <cuda_fp16.h>
#include <cstdint>

#define NN 100000
#define EE 1600000
#define DD 64
#define NB 98            // ceil(NN/1024)
#define GEMM_BLOCKS 782  // ceil(NN/128)
#define DEG_BLOCKS 1563  // ceil(EE/1024), 4 edges/thread
#define BIN_BLOCKS 782   // ceil(EE/2048), 8 edges/thread

// ---------------- device scratch (zero-initialized at module load) ----------
__device__ int    g_degi[NN];      // in-degree; reset by gather for next call
__device__ int    g_start[NN];
__device__ float  g_dinv[NN];
__device__ float  g_invdeg[NN];
__device__ int    g_rank[EE];
__device__ int    g_csr[EE];
__device__ __half2 g_yh[NN * 32];  // y = x @ W^T in fp16 (row-major)
__device__ unsigned long long g_state[NB];
__device__ int    g_ticket;

// ---------------------------------------------------------------------------
__device__ __forceinline__ unsigned f2tf32(float f) {
    unsigned u;
    asm("cvt.rna.tf32.f32 %0, %1;" : "=r"(u) : "f"(f));
    return u;
}

__device__ __forceinline__ void mma_tf32(float acc[4], unsigned a0, unsigned a1,
                                         unsigned a2, unsigned a3,
                                         unsigned b0, unsigned b1) {
    asm volatile(
        "mma.sync.aligned.m16n8k8.row.col.f32.tf32.tf32.f32 "
        "{%0,%1,%2,%3}, {%4,%5,%6,%7}, {%8,%9}, {%0,%1,%2,%3};"
        : "+f"(acc[0]), "+f"(acc[1]), "+f"(acc[2]), "+f"(acc[3])
        : "r"(a0), "r"(a1), "r"(a2), "r"(a3), "r"(b0), "r"(b1));
}

// Fused: blocks [0,GEMM_BLOCKS): y = x @ W^T (tf32 MMA, fp16 store)
//        blocks [GEMM_BLOCKS,+DEG_BLOCKS): degree histogram + rank capture.
//        First deg block re-arms the scan state for this call.
__global__ __launch_bounds__(256) void fused_gemm_deg_kernel(
        const float* __restrict__ W, const float* __restrict__ x,
        const int* __restrict__ col) {
    __shared__ unsigned sW[64 * 68];
    int tid = threadIdx.x;

    if (blockIdx.x >= GEMM_BLOCKS) {
        int dblk = blockIdx.x - GEMM_BLOCKS;
        if (dblk == 0) {
            if (tid < NB) g_state[tid] = 0ULL;
            if (tid == NB) g_ticket = 0;
        }
        int base = dblk * 1024;
        #pragma unroll
        for (int u = 0; u < 4; u++) {
            int e = base + u * 256 + tid;
            if (e < EE) g_rank[e] = atomicAdd(&g_degi[col[e]], 1);
        }
        return;
    }

    #pragma unroll
    for (int t = tid; t < 4096; t += 256) {
        int n = t >> 6, k = t & 63;
        sW[n * 68 + k] = f2tf32(W[t]);
    }
    __syncthreads();

    int warp = tid >> 5, lane = tid & 31;
    int gid = lane >> 2, tg = lane & 3;
    int r0 = blockIdx.x * 128 + warp * 16;
    int rA = r0 + gid;
    int rB = rA + 8;
    int rAc = rA < NN ? rA : NN - 1;
    int rBc = rB < NN ? rB : NN - 1;
    const float* pA = x + rAc * 64 + tg;
    const float* pB = x + rBc * 64 + tg;

    float acc[8][4];
    #pragma unroll
    for (int n = 0; n < 8; n++)
        #pragma unroll
        for (int j = 0; j < 4; j++) acc[n][j] = 0.0f;

    #pragma unroll
    for (int s = 0; s < 8; s++) {
        int k0 = s * 8;
        unsigned a0 = f2tf32(pA[k0]);
        unsigned a1 = f2tf32(pB[k0]);
        unsigned a2 = f2tf32(pA[k0 + 4]);
        unsigned a3 = f2tf32(pB[k0 + 4]);
        #pragma unroll
        for (int n = 0; n < 8; n++) {
            unsigned b0 = sW[(n * 8 + gid) * 68 + k0 + tg];
            unsigned b1 = sW[(n * 8 + gid) * 68 + k0 + tg + 4];
            mma_tf32(acc[n], a0, a1, a2, a3, b0, b1);
        }
    }

    #pragma unroll
    for (int n = 0; n < 8; n++) {
        int cidx = n * 4 + tg;
        if (rA < NN) g_yh[rA * 32 + cidx] = __floats2half2_rn(acc[n][0], acc[n][1]);
        if (rB < NN) g_yh[rB * 32 + cidx] = __floats2half2_rn(acc[n][2], acc[n][3]);
    }
}

// ---------------------------------------------------------------------------
// Single-pass decoupled-lookback scan + finalize dinv/invdeg.
__global__ void scan_kernel() {
    __shared__ int wsum[32];
    __shared__ int sh_tile;
    __shared__ int sh_prefix;
    int tid = threadIdx.x, lane = tid & 31, wid = tid >> 5;

    if (tid == 0) sh_tile = atomicAdd(&g_ticket, 1);
    __syncthreads();
    int tile = sh_tile;
    int i = tile * 1024 + tid;
    int v = (i < NN) ? g_degi[i] : 0;

    int xs = v;
    #pragma unroll
    for (int d = 1; d < 32; d <<= 1) {
        int t = __shfl_up_sync(0xffffffffu, xs, d);
        if (lane >= d) xs += t;
    }
    if (lane == 31) wsum[wid] = xs;
    __syncthreads();
    if (wid == 0) {
        int s = wsum[lane];
        #pragma unroll
        for (int d = 1; d < 32; d <<= 1) {
            int t = __shfl_up_sync(0xffffffffu, s, d);
            if (lane >= d) s += t;
        }
        wsum[lane] = s;
    }
    __syncthreads();
    int incl = xs + (wid ? wsum[wid - 1] : 0);
    int total = wsum[31];

    if (tid == 0) {
        unsigned long long pack =
            ((unsigned long long)(tile == 0 ? 2u : 1u) << 32) | (unsigned)total;
        atomicExch(&g_state[tile], pack);
    }

    if (wid == 0) {
        int prefix = 0;
        if (tile > 0) {
            int base = tile - 1;
            while (true) {
                int t = base - lane;
                unsigned long long s;
                if (t >= 0) {
                    do { s = atomicAdd(&g_state[t], 0ULL); } while ((unsigned)(s >> 32) == 0u);
                } else {
                    s = (2ULL << 32);
                }
                unsigned flag = (unsigned)(s >> 32);
                int val = (int)(unsigned)s;
                unsigned ball = __ballot_sync(0xffffffffu, flag == 2u);
                int firstInc = __ffs(ball) - 1;
                int contrib = ball ? ((lane <= firstInc) ? val : 0) : val;
                #pragma unroll
                for (int d = 16; d; d >>= 1)
                    contrib += __shfl_xor_sync(0xffffffffu, contrib, d);
                prefix += contrib;
                if (ball) break;
                base -= 32;
            }
            if (lane == 0)
                atomicExch(&g_state[tile],
                           (2ULL << 32) | (unsigned)(prefix + total));
        }
        if (lane == 0) sh_prefix = prefix;
    }
    __syncthreads();
    int prefix = sh_prefix;
    if (i < NN) {
        g_start[i] = prefix + incl - v;
        float df = (float)v + 1.0f;
        g_dinv[i]   = rsqrtf(df);
        g_invdeg[i] = 1.0f / df;
    }
}

// ---------------------------------------------------------------------------
// bin: atomic-free CSR placement. 8 edges/thread, loads batched for MLP.
__global__ __launch_bounds__(256) void bin_kernel(const int* __restrict__ row,
                                                  const int* __restrict__ col) {
    int base = blockIdx.x * 2048 + threadIdx.x;
    int cs[8], rk[8], rw[8];
    #pragma unroll
    for (int u = 0; u < 8; u++) {
        int e = base + u * 256;
        if (e < EE) { cs[u] = col[e]; rk[u] = g_rank[e]; rw[u] = row[e]; }
        else cs[u] = -1;
    }
    int st[8];
    #pragma unroll
    for (int u = 0; u < 8; u++)
        if (cs[u] >= 0) st[u] = g_start[cs[u]];
    #pragma unroll
    for (int u = 0; u < 8; u++)
        if (cs[u] >= 0) g_csr[st[u] + rk[u]] = rw[u];
}

// ---------------------------------------------------------------------------
// gather: ONE WARP PER NODE. Lane = (edge-slot eg = lid>>3) x (col-block j = lid&7).
// Per step the warp consumes 4 edges of its node; j-lanes read one coalesced
// 128B fp16 row per edge. 2-deep software pipeline; shfl_xor(8,16) folds the
// 4 edge-slots at the end. Resets g_degi for the next call.
__global__ __launch_bounds__(256) void gather_kernel(const float* __restrict__ bias,
                                                     float4* __restrict__ out4) {
    int lid  = threadIdx.x & 31;
    int warp = threadIdx.x >> 5;
    int c = blockIdx.x * 8 + warp;
    if (c >= NN) return;
    int eg = lid >> 3;          // edge slot 0..3
    int j  = lid & 7;           // column block (uint4 = 8 fp16 cols)

    int start = g_start[c];
    int cnt   = g_degi[c];
    if (lid == 0) g_degi[c] = 0;

    const uint4* Y = (const uint4*)g_yh;

    float a0=0,a1=0,a2=0,a3=0,a4=0,a5=0,a6=0,a7=0;

    if (cnt > 0) {
        // stage 0
        int e = eg;
        int ee = e < cnt ? e : cnt - 1;
        int   s = g_csr[start + ee];
        float w = (e < cnt) ? g_dinv[s] : 0.0f;
        uint4 v = Y[s * 8 + j];

        int k = 0;
        while (true) {
            int kn = k + 4;
            bool more = kn < cnt;        // uniform across warp
            int s2; float w2; uint4 v2;
            if (more) {
                int e2 = kn + eg;
                int ee2 = e2 < cnt ? e2 : cnt - 1;
                s2 = g_csr[start + ee2];
                w2 = (e2 < cnt) ? g_dinv[s2] : 0.0f;
                v2 = Y[s2 * 8 + j];
            }
            // consume current
            {
                float2 p;
                p = __half22float2(*(__half2*)&v.x); a0 += w*p.x; a1 += w*p.y;
                p = __half22float2(*(__half2*)&v.y); a2 += w*p.x; a3 += w*p.y;
                p = __half22float2(*(__half2*)&v.z); a4 += w*p.x; a5 += w*p.y;
                p = __half22float2(*(__half2*)&v.w); a6 += w*p.x; a7 += w*p.y;
            }
            if (!more) break;
            s = s2; w = w2; v = v2; k = kn;
        }
    }

    // fold the 4 edge slots (lane bits 3 and 4)
    #pragma unroll
    for (int d = 8; d <= 16; d <<= 1) {
        a0 += __shfl_xor_sync(0xffffffffu, a0, d);
        a1 += __shfl_xor_sync(0xffffffffu, a1, d);
        a2 += __shfl_xor_sync(0xffffffffu, a2, d);
        a3 += __shfl_xor_sync(0xffffffffu, a3, d);
        a4 += __shfl_xor_sync(0xffffffffu, a4, d);
        a5 += __shfl_xor_sync(0xffffffffu, a5, d);
        a6 += __shfl_xor_sync(0xffffffffu, a6, d);
        a7 += __shfl_xor_sync(0xffffffffu, a7, d);
    }

    if (eg == 0) {                       // lanes 0..7, j = lid
        float dc  = g_dinv[c];
        float inv = g_invdeg[c];
        uint4 sv = Y[c * 8 + j];
        const float4* b4 = (const float4*)bias;
        float4 ba = b4[2 * j], bb = b4[2 * j + 1];

        float2 p;
        float4 o0, o1;
        p = __half22float2(*(__half2*)&sv.x); o0.x = dc*a0 + inv*p.x + ba.x; o0.y = dc*a1 + inv*p.y + ba.y;
        p = __half22float2(*(__half2*)&sv.y); o0.z = dc*a2 + inv*p.x + ba.z; o0.w = dc*a3 + inv*p.y + ba.w;
        p = __half22float2(*(__half2*)&sv.z); o1.x = dc*a4 + inv*p.x + bb.x; o1.y = dc*a5 + inv*p.y + bb.y;
        p = __half22float2(*(__half2*)&sv.w); o1.z = dc*a6 + inv*p.x + bb.z; o1.w = dc*a7 + inv*p.y + bb.w;

        out4[c * 16 + 2 * j]     = o0;
        out4[c * 16 + 2 * j + 1] = o1;
    }
}

// ---------------------------------------------------------------------------
extern "C" void kernel_launch(void* const* d_in, const int* in_sizes, int n_in,
                              void* d_out, int out_size) {
    const float* x  = nullptr;
    const int*   ei = nullptr;
    const float* Ww = nullptr;
    const float* Wb = nullptr;
    for (int i = 0; i < n_in; i++) {
        int sz = in_sizes[i];
        if (sz == 2 * EE)             ei = (const int*)d_in[i];
        else if (sz == DD * DD)       Ww = (const float*)d_in[i];
        else if (sz == DD)            Wb = (const float*)d_in[i];
        else if (sz == NN * DD && !x) x  = (const float*)d_in[i];
    }
    const int* row = ei;          // sources
    const int* col = ei + EE;     // targets
    float4* out4 = (float4*)d_out;

    fused_gemm_deg_kernel<<<GEMM_BLOCKS + DEG_BLOCKS, 256>>>(Ww, x, col);
    scan_kernel          <<<NB, 1024>>>();
    bin_kernel           <<<BIN_BLOCKS, 256>>>(row, col);
    gather_kernel        <<<(NN + 7) / 8, 256>>>(Wb, out4);
}

// round 8
// speedup vs baseline: 1.3076x; 1.3076x over previous
#include <cuda_runtime.h>
#include <cuda_fp16.h>
#include <cstdint>

#define NN 100000
#define EE 1600000
#define DD 64
#define NB 98            // ceil(NN/1024)
#define GEMM_BLOCKS 782  // ceil(NN/128)
#define DEG_BLOCKS 1563  // ceil(EE/1024), 4 edges/thread
#define BIN_BLOCKS 782   // ceil(EE/2048), 8 edges/thread

// ---------------- device scratch (zero-initialized at module load) ----------
__device__ int    g_degi[NN];      // in-degree; reset by gather for next call
__device__ int    g_start[NN];
__device__ float  g_dinv[NN];
__device__ float  g_invdeg[NN];
__device__ int    g_rank[EE];
__device__ int    g_csr[EE];
__device__ __half2 g_yh[NN * 32];  // y = x @ W^T in fp16 (row-major, 128B/row)
__device__ unsigned long long g_state[NB];
__device__ int    g_ticket;

// ---------------------------------------------------------------------------
__device__ __forceinline__ unsigned f2tf32(float f) {
    unsigned u;
    asm("cvt.rna.tf32.f32 %0, %1;" : "=r"(u) : "f"(f));
    return u;
}

__device__ __forceinline__ void mma_tf32(float acc[4], unsigned a0, unsigned a1,
                                         unsigned a2, unsigned a3,
                                         unsigned b0, unsigned b1) {
    asm volatile(
        "mma.sync.aligned.m16n8k8.row.col.f32.tf32.tf32.f32 "
        "{%0,%1,%2,%3}, {%4,%5,%6,%7}, {%8,%9}, {%0,%1,%2,%3};"
        : "+f"(acc[0]), "+f"(acc[1]), "+f"(acc[2]), "+f"(acc[3])
        : "r"(a0), "r"(a1), "r"(a2), "r"(a3), "r"(b0), "r"(b1));
}

// Fused: blocks [0,GEMM_BLOCKS): y = x @ W^T (tf32 MMA, fp16 store)
//        blocks [GEMM_BLOCKS,+DEG_BLOCKS): degree histogram + rank capture.
//        First deg block re-arms the scan state for this call.
__global__ __launch_bounds__(256) void fused_gemm_deg_kernel(
        const float* __restrict__ W, const float* __restrict__ x,
        const int* __restrict__ col) {
    __shared__ unsigned sW[64 * 68];
    int tid = threadIdx.x;

    if (blockIdx.x >= GEMM_BLOCKS) {
        int dblk = blockIdx.x - GEMM_BLOCKS;
        if (dblk == 0) {
            if (tid < NB) g_state[tid] = 0ULL;
            if (tid == NB) g_ticket = 0;
        }
        int base = dblk * 1024;
        #pragma unroll
        for (int u = 0; u < 4; u++) {
            int e = base + u * 256 + tid;
            if (e < EE) g_rank[e] = atomicAdd(&g_degi[col[e]], 1);
        }
        return;
    }

    #pragma unroll
    for (int t = tid; t < 4096; t += 256) {
        int n = t >> 6, k = t & 63;
        sW[n * 68 + k] = f2tf32(W[t]);
    }
    __syncthreads();

    int warp = tid >> 5, lane = tid & 31;
    int gid = lane >> 2, tg = lane & 3;
    int r0 = blockIdx.x * 128 + warp * 16;
    int rA = r0 + gid;
    int rB = rA + 8;
    int rAc = rA < NN ? rA : NN - 1;
    int rBc = rB < NN ? rB : NN - 1;
    const float* pA = x + rAc * 64 + tg;
    const float* pB = x + rBc * 64 + tg;

    float acc[8][4];
    #pragma unroll
    for (int n = 0; n < 8; n++)
        #pragma unroll
        for (int j = 0; j < 4; j++) acc[n][j] = 0.0f;

    #pragma unroll
    for (int s = 0; s < 8; s++) {
        int k0 = s * 8;
        unsigned a0 = f2tf32(pA[k0]);
        unsigned a1 = f2tf32(pB[k0]);
        unsigned a2 = f2tf32(pA[k0 + 4]);
        unsigned a3 = f2tf32(pB[k0 + 4]);
        #pragma unroll
        for (int n = 0; n < 8; n++) {
            unsigned b0 = sW[(n * 8 + gid) * 68 + k0 + tg];
            unsigned b1 = sW[(n * 8 + gid) * 68 + k0 + tg + 4];
            mma_tf32(acc[n], a0, a1, a2, a3, b0, b1);
        }
    }

    #pragma unroll
    for (int n = 0; n < 8; n++) {
        int cidx = n * 4 + tg;
        if (rA < NN) g_yh[rA * 32 + cidx] = __floats2half2_rn(acc[n][0], acc[n][1]);
        if (rB < NN) g_yh[rB * 32 + cidx] = __floats2half2_rn(acc[n][2], acc[n][3]);
    }
}

// ---------------------------------------------------------------------------
// Single-pass decoupled-lookback scan + finalize dinv/invdeg.
__global__ void scan_kernel() {
    __shared__ int wsum[32];
    __shared__ int sh_tile;
    __shared__ int sh_prefix;
    int tid = threadIdx.x, lane = tid & 31, wid = tid >> 5;

    if (tid == 0) sh_tile = atomicAdd(&g_ticket, 1);
    __syncthreads();
    int tile = sh_tile;
    int i = tile * 1024 + tid;
    int v = (i < NN) ? g_degi[i] : 0;

    int xs = v;
    #pragma unroll
    for (int d = 1; d < 32; d <<= 1) {
        int t = __shfl_up_sync(0xffffffffu, xs, d);
        if (lane >= d) xs += t;
    }
    if (lane == 31) wsum[wid] = xs;
    __syncthreads();
    if (wid == 0) {
        int s = wsum[lane];
        #pragma unroll
        for (int d = 1; d < 32; d <<= 1) {
            int t = __shfl_up_sync(0xffffffffu, s, d);
            if (lane >= d) s += t;
        }
        wsum[lane] = s;
    }
    __syncthreads();
    int incl = xs + (wid ? wsum[wid - 1] : 0);
    int total = wsum[31];

    if (tid == 0) {
        unsigned long long pack =
            ((unsigned long long)(tile == 0 ? 2u : 1u) << 32) | (unsigned)total;
        atomicExch(&g_state[tile], pack);
    }

    if (wid == 0) {
        int prefix = 0;
        if (tile > 0) {
            int base = tile - 1;
            while (true) {
                int t = base - lane;
                unsigned long long s;
                if (t >= 0) {
                    do { s = atomicAdd(&g_state[t], 0ULL); } while ((unsigned)(s >> 32) == 0u);
                } else {
                    s = (2ULL << 32);
                }
                unsigned flag = (unsigned)(s >> 32);
                int val = (int)(unsigned)s;
                unsigned ball = __ballot_sync(0xffffffffu, flag == 2u);
                int firstInc = __ffs(ball) - 1;
                int contrib = ball ? ((lane <= firstInc) ? val : 0) : val;
                #pragma unroll
                for (int d = 16; d; d >>= 1)
                    contrib += __shfl_xor_sync(0xffffffffu, contrib, d);
                prefix += contrib;
                if (ball) break;
                base -= 32;
            }
            if (lane == 0)
                atomicExch(&g_state[tile],
                           (2ULL << 32) | (unsigned)(prefix + total));
        }
        if (lane == 0) sh_prefix = prefix;
    }
    __syncthreads();
    int prefix = sh_prefix;
    if (i < NN) {
        g_start[i] = prefix + incl - v;
        float df = (float)v + 1.0f;
        g_dinv[i]   = rsqrtf(df);
        g_invdeg[i] = 1.0f / df;
    }
}

// ---------------------------------------------------------------------------
// bin: atomic-free CSR placement. 8 edges/thread, loads batched for MLP.
__global__ __launch_bounds__(256) void bin_kernel(const int* __restrict__ row,
                                                  const int* __restrict__ col) {
    int base = blockIdx.x * 2048 + threadIdx.x;
    int cs[8], rk[8], rw[8];
    #pragma unroll
    for (int u = 0; u < 8; u++) {
        int e = base + u * 256;
        if (e < EE) { cs[u] = col[e]; rk[u] = g_rank[e]; rw[u] = row[e]; }
        else cs[u] = -1;
    }
    int st[8];
    #pragma unroll
    for (int u = 0; u < 8; u++)
        if (cs[u] >= 0) st[u] = g_start[cs[u]];
    #pragma unroll
    for (int u = 0; u < 8; u++)
        if (cs[u] >= 0) g_csr[st[u] + rk[u]] = rw[u];
}

// ---------------------------------------------------------------------------
// gather: 16 threads/node (2 nodes per warp). Chunked cp.async pipeline:
// per chunk of 8 edges, lanes 0-7 (node A) / 16-23 (node B) cooperatively
// load csr+dinv into smem, then every lane issues 8 cp.async 8B stages of its
// column slice, waits once, and consumes from smem. Tail edges use w=0
// against real staged data. Register footprint stays minimal.
#define PDEPTH 8
__global__ __launch_bounds__(256) void gather_kernel(const float* __restrict__ bias,
                                                     float4* __restrict__ out4) {
    __shared__ uint2 sy[PDEPTH][256];        // 16 KB staged y slices
    __shared__ int   ssrc[8][2][PDEPTH];     // per-warp per-node sources
    __shared__ float swt [8][2][PDEPTH];     // per-warp per-node weights

    int tid  = threadIdx.x;
    int wid  = tid >> 5;
    int lid  = tid & 31;
    int half = lid >> 4;                     // node within warp
    int j    = lid & 15;                     // column slice (uint2 = 4 fp16)
    int c    = blockIdx.x * 16 + (tid >> 4);
    if (c >= NN) return;

    int start = g_start[c];
    int cnt   = g_degi[c];
    if (j == 0) g_degi[c] = 0;

    int cother = __shfl_xor_sync(0xffffffffu, cnt, 16);
    int cmax = cnt > cother ? cnt : cother;

    const uint2* Y2 = (const uint2*)g_yh;    // row r -> Y2[r*16 + j]
    float a0 = 0.f, a1 = 0.f, a2 = 0.f, a3 = 0.f;

    unsigned dst_base = (unsigned)__cvta_generic_to_shared(&sy[0][tid]);

    for (int k0 = 0; k0 < cmax; k0 += PDEPTH) {
        // cooperative csr+dinv staging: lanes with (lid&8)==0, index lid&7
        if ((lid & 8) == 0) {
            int i = lid & 7;
            int e = k0 + i;
            int s = 0; float w = 0.f;
            if (e < cnt) { s = g_csr[start + e]; w = g_dinv[s]; }
            ssrc[wid][half][i] = s;
            swt [wid][half][i] = w;
        }
        __syncwarp();
        // stage 8 y-slices via cp.async (8B each)
        #pragma unroll
        for (int i = 0; i < PDEPTH; i++) {
            int s = ssrc[wid][half][i];
            const uint2* src = Y2 + s * 16 + j;
            unsigned dst = dst_base + (unsigned)(i * 256 * sizeof(uint2));
            asm volatile("cp.async.ca.shared.global [%0], [%1], 8;"
                         :: "r"(dst), "l"(src) : "memory");
        }
        asm volatile("cp.async.commit_group;" ::: "memory");
        asm volatile("cp.async.wait_group 0;" ::: "memory");
        // consume
        #pragma unroll
        for (int i = 0; i < PDEPTH; i++) {
            float w = swt[wid][half][i];
            uint2 v = sy[i][tid];
            float2 p0 = __half22float2(*(__half2*)&v.x);
            float2 p1 = __half22float2(*(__half2*)&v.y);
            a0 += w * p0.x; a1 += w * p0.y;
            a2 += w * p1.x; a3 += w * p1.y;
        }
        __syncwarp();
    }

    float dc  = g_dinv[c];
    float inv = g_invdeg[c];
    uint2 sv = Y2[c * 16 + j];
    float2 s0 = __half22float2(*(__half2*)&sv.x);
    float2 s1 = __half22float2(*(__half2*)&sv.y);
    float4 b4 = ((const float4*)bias)[j];

    float4 o;
    o.x = dc * a0 + inv * s0.x + b4.x;
    o.y = dc * a1 + inv * s0.y + b4.y;
    o.z = dc * a2 + inv * s1.x + b4.z;
    o.w = dc * a3 + inv * s1.y + b4.w;
    out4[c * 16 + j] = o;
}

// ---------------------------------------------------------------------------
extern "C" void kernel_launch(void* const* d_in, const int* in_sizes, int n_in,
                              void* d_out, int out_size) {
    const float* x  = nullptr;
    const int*   ei = nullptr;
    const float* Ww = nullptr;
    const float* Wb = nullptr;
    for (int i = 0; i < n_in; i++) {
        int sz = in_sizes[i];
        if (sz == 2 * EE)             ei = (const int*)d_in[i];
        else if (sz == DD * DD)       Ww = (const float*)d_in[i];
        else if (sz == DD)            Wb = (const float*)d_in[i];
        else if (sz == NN * DD && !x) x  = (const float*)d_in[i];
    }
    const int* row = ei;          // sources
    const int* col = ei + EE;     // targets
    float4* out4 = (float4*)d_out;

    fused_gemm_deg_kernel<<<GEMM_BLOCKS + DEG_BLOCKS, 256>>>(Ww, x, col);
    scan_kernel          <<<NB, 1024>>>();
    bin_kernel           <<<BIN_BLOCKS, 256>>>(row, col);
    gather_kernel        <<<(NN + 15) / 16, 256>>>(Wb, out4);
}

// round 9
// speedup vs baseline: 2.0682x; 1.5818x over previous
#include <cuda_runtime.h>
#include <cuda_fp16.h>
#include <cstdint>

#define NN 100000
#define EE 1600000
#define DD 64
#define NB 98            // ceil(NN/1024)
#define GEMM_BLOCKS 782  // ceil(NN/128)
#define DEG_BLOCKS 1563  // ceil(EE/1024), 4 edges/thread
#define BIN_BLOCKS 782   // ceil(EE/2048), 8 edges/thread

// ---------------- device scratch (zero-initialized at module load) ----------
__device__ int    g_degi[NN];      // in-degree; reset by gather for next call
__device__ int    g_start[NN];
__device__ float  g_dinv[NN];
__device__ int    g_rank[EE];
__device__ int    g_csr[EE];
__device__ __half2 g_yh[NN * 32];  // ys = dinv[r] * (x @ W^T)[r], fp16, 128B/row
__device__ unsigned long long g_state[NB];
__device__ int    g_ticket;

// ---------------------------------------------------------------------------
// deg: histogram + rank capture; block 0 re-arms scan state.
__global__ __launch_bounds__(256) void deg_kernel(const int* __restrict__ col) {
    int tid = threadIdx.x;
    if (blockIdx.x == 0) {
        if (tid < NB) g_state[tid] = 0ULL;
        if (tid == NB) g_ticket = 0;
    }
    int base = blockIdx.x * 1024;
    #pragma unroll
    for (int u = 0; u < 4; u++) {
        int e = base + u * 256 + tid;
        if (e < EE) g_rank[e] = atomicAdd(&g_degi[col[e]], 1);
    }
}

// ---------------------------------------------------------------------------
// Single-pass decoupled-lookback scan + finalize dinv.
__global__ void scan_kernel() {
    __shared__ int wsum[32];
    __shared__ int sh_tile;
    __shared__ int sh_prefix;
    int tid = threadIdx.x, lane = tid & 31, wid = tid >> 5;

    if (tid == 0) sh_tile = atomicAdd(&g_ticket, 1);
    __syncthreads();
    int tile = sh_tile;
    int i = tile * 1024 + tid;
    int v = (i < NN) ? g_degi[i] : 0;

    int xs = v;
    #pragma unroll
    for (int d = 1; d < 32; d <<= 1) {
        int t = __shfl_up_sync(0xffffffffu, xs, d);
        if (lane >= d) xs += t;
    }
    if (lane == 31) wsum[wid] = xs;
    __syncthreads();
    if (wid == 0) {
        int s = wsum[lane];
        #pragma unroll
        for (int d = 1; d < 32; d <<= 1) {
            int t = __shfl_up_sync(0xffffffffu, s, d);
            if (lane >= d) s += t;
        }
        wsum[lane] = s;
    }
    __syncthreads();
    int incl = xs + (wid ? wsum[wid - 1] : 0);
    int total = wsum[31];

    if (tid == 0) {
        unsigned long long pack =
            ((unsigned long long)(tile == 0 ? 2u : 1u) << 32) | (unsigned)total;
        atomicExch(&g_state[tile], pack);
    }

    if (wid == 0) {
        int prefix = 0;
        if (tile > 0) {
            int base = tile - 1;
            while (true) {
                int t = base - lane;
                unsigned long long s;
                if (t >= 0) {
                    do { s = atomicAdd(&g_state[t], 0ULL); } while ((unsigned)(s >> 32) == 0u);
                } else {
                    s = (2ULL << 32);
                }
                unsigned flag = (unsigned)(s >> 32);
                int val = (int)(unsigned)s;
                unsigned ball = __ballot_sync(0xffffffffu, flag == 2u);
                int firstInc = __ffs(ball) - 1;
                int contrib = ball ? ((lane <= firstInc) ? val : 0) : val;
                #pragma unroll
                for (int d = 16; d; d >>= 1)
                    contrib += __shfl_xor_sync(0xffffffffu, contrib, d);
                prefix += contrib;
                if (ball) break;
                base -= 32;
            }
            if (lane == 0)
                atomicExch(&g_state[tile],
                           (2ULL << 32) | (unsigned)(prefix + total));
        }
        if (lane == 0) sh_prefix = prefix;
    }
    __syncthreads();
    int prefix = sh_prefix;
    if (i < NN) {
        g_start[i] = prefix + incl - v;
        g_dinv[i] = rsqrtf((float)v + 1.0f);   // + self loop
    }
}

// ---------------------------------------------------------------------------
__device__ __forceinline__ unsigned f2tf32(float f) {
    unsigned u;
    asm("cvt.rna.tf32.f32 %0, %1;" : "=r"(u) : "f"(f));
    return u;
}

__device__ __forceinline__ void mma_tf32(float acc[4], unsigned a0, unsigned a1,
                                         unsigned a2, unsigned a3,
                                         unsigned b0, unsigned b1) {
    asm volatile(
        "mma.sync.aligned.m16n8k8.row.col.f32.tf32.tf32.f32 "
        "{%0,%1,%2,%3}, {%4,%5,%6,%7}, {%8,%9}, {%0,%1,%2,%3};"
        : "+f"(acc[0]), "+f"(acc[1]), "+f"(acc[2]), "+f"(acc[3])
        : "r"(a0), "r"(a1), "r"(a2), "r"(a3), "r"(b0), "r"(b1));
}

// Fused: blocks [0,GEMM_BLOCKS): ys = dinv * (x @ W^T) (tf32 MMA, fp16 store)
//        blocks [GEMM_BLOCKS,+BIN_BLOCKS): CSR placement via ranks.
__global__ __launch_bounds__(256) void fused_gemm_bin_kernel(
        const float* __restrict__ W, const float* __restrict__ x,
        const int* __restrict__ row, const int* __restrict__ col) {
    __shared__ unsigned sW[64 * 68];
    int tid = threadIdx.x;

    if (blockIdx.x >= GEMM_BLOCKS) {
        int base = (blockIdx.x - GEMM_BLOCKS) * 2048 + tid;
        int cs[8], rk[8], rw[8];
        #pragma unroll
        for (int u = 0; u < 8; u++) {
            int e = base + u * 256;
            if (e < EE) { cs[u] = col[e]; rk[u] = g_rank[e]; rw[u] = row[e]; }
            else cs[u] = -1;
        }
        int st[8];
        #pragma unroll
        for (int u = 0; u < 8; u++)
            if (cs[u] >= 0) st[u] = g_start[cs[u]];
        #pragma unroll
        for (int u = 0; u < 8; u++)
            if (cs[u] >= 0) g_csr[st[u] + rk[u]] = rw[u];
        return;
    }

    #pragma unroll
    for (int t = tid; t < 4096; t += 256) {
        int n = t >> 6, k = t & 63;
        sW[n * 68 + k] = f2tf32(W[t]);
    }
    __syncthreads();

    int warp = tid >> 5, lane = tid & 31;
    int gid = lane >> 2, tg = lane & 3;
    int r0 = blockIdx.x * 128 + warp * 16;
    int rA = r0 + gid;
    int rB = rA + 8;
    int rAc = rA < NN ? rA : NN - 1;
    int rBc = rB < NN ? rB : NN - 1;
    const float* pA = x + rAc * 64 + tg;
    const float* pB = x + rBc * 64 + tg;

    float acc[8][4];
    #pragma unroll
    for (int n = 0; n < 8; n++)
        #pragma unroll
        for (int j = 0; j < 4; j++) acc[n][j] = 0.0f;

    #pragma unroll
    for (int s = 0; s < 8; s++) {
        int k0 = s * 8;
        unsigned a0 = f2tf32(pA[k0]);
        unsigned a1 = f2tf32(pB[k0]);
        unsigned a2 = f2tf32(pA[k0 + 4]);
        unsigned a3 = f2tf32(pB[k0 + 4]);
        #pragma unroll
        for (int n = 0; n < 8; n++) {
            unsigned b0 = sW[(n * 8 + gid) * 68 + k0 + tg];
            unsigned b1 = sW[(n * 8 + gid) * 68 + k0 + tg + 4];
            mma_tf32(acc[n], a0, a1, a2, a3, b0, b1);
        }
    }

    float dA = g_dinv[rAc];
    float dB = g_dinv[rBc];
    #pragma unroll
    for (int n = 0; n < 8; n++) {
        int cidx = n * 4 + tg;
        if (rA < NN) g_yh[rA * 32 + cidx] = __floats2half2_rn(dA * acc[n][0], dA * acc[n][1]);
        if (rB < NN) g_yh[rB * 32 + cidx] = __floats2half2_rn(dB * acc[n][2], dB * acc[n][3]);
    }
}

// ---------------------------------------------------------------------------
// gather: 8 threads/node, flat unroll-4. Inner loop = csr load + 16B y load +
// fp32 adds — no weights (y is pre-scaled by dinv[src]; self loop folds in).
// out[c] = dinv[c] * (sum_r ys[r] + ys[c]) + bias. Resets g_degi.
__global__ __launch_bounds__(256, 6) void gather_kernel(const float* __restrict__ bias,
                                                        float4* __restrict__ out4) {
    int t = blockIdx.x * 256 + threadIdx.x;
    int c = t >> 3;
    if (c >= NN) return;
    int j = t & 7;

    int start = g_start[c];
    int cnt   = g_degi[c];
    if (j == 0) g_degi[c] = 0;

    const uint4* Y = (const uint4*)g_yh;   // row r -> Y[r*8 + j]

    float a0=0,a1=0,a2=0,a3=0,a4=0,a5=0,a6=0,a7=0;

    int k = 0;
    for (; k + 4 <= cnt; k += 4) {
        int s0 = g_csr[start + k];
        int s1 = g_csr[start + k + 1];
        int s2 = g_csr[start + k + 2];
        int s3 = g_csr[start + k + 3];
        uint4 v0 = Y[s0 * 8 + j];
        uint4 v1 = Y[s1 * 8 + j];
        uint4 v2 = Y[s2 * 8 + j];
        uint4 v3 = Y[s3 * 8 + j];
        float2 p;
        p = __half22float2(*(__half2*)&v0.x); a0 += p.x; a1 += p.y;
        p = __half22float2(*(__half2*)&v0.y); a2 += p.x; a3 += p.y;
        p = __half22float2(*(__half2*)&v0.z); a4 += p.x; a5 += p.y;
        p = __half22float2(*(__half2*)&v0.w); a6 += p.x; a7 += p.y;
        p = __half22float2(*(__half2*)&v1.x); a0 += p.x; a1 += p.y;
        p = __half22float2(*(__half2*)&v1.y); a2 += p.x; a3 += p.y;
        p = __half22float2(*(__half2*)&v1.z); a4 += p.x; a5 += p.y;
        p = __half22float2(*(__half2*)&v1.w); a6 += p.x; a7 += p.y;
        p = __half22float2(*(__half2*)&v2.x); a0 += p.x; a1 += p.y;
        p = __half22float2(*(__half2*)&v2.y); a2 += p.x; a3 += p.y;
        p = __half22float2(*(__half2*)&v2.z); a4 += p.x; a5 += p.y;
        p = __half22float2(*(__half2*)&v2.w); a6 += p.x; a7 += p.y;
        p = __half22float2(*(__half2*)&v3.x); a0 += p.x; a1 += p.y;
        p = __half22float2(*(__half2*)&v3.y); a2 += p.x; a3 += p.y;
        p = __half22float2(*(__half2*)&v3.z); a4 += p.x; a5 += p.y;
        p = __half22float2(*(__half2*)&v3.w); a6 += p.x; a7 += p.y;
    }
    for (; k < cnt; k++) {
        int s = g_csr[start + k];
        uint4 v = Y[s * 8 + j];
        float2 p;
        p = __half22float2(*(__half2*)&v.x); a0 += p.x; a1 += p.y;
        p = __half22float2(*(__half2*)&v.y); a2 += p.x; a3 += p.y;
        p = __half22float2(*(__half2*)&v.z); a4 += p.x; a5 += p.y;
        p = __half22float2(*(__half2*)&v.w); a6 += p.x; a7 += p.y;
    }

    // self term: + ys[c], then scale by dinv[c], add bias
    float dc = g_dinv[c];
    uint4 sv = Y[c * 8 + j];
    const float4* b4 = (const float4*)bias;
    float4 ba = b4[2 * j], bb = b4[2 * j + 1];

    float2 p;
    float4 o0, o1;
    p = __half22float2(*(__half2*)&sv.x); o0.x = dc*(a0 + p.x) + ba.x; o0.y = dc*(a1 + p.y) + ba.y;
    p = __half22float2(*(__half2*)&sv.y); o0.z = dc*(a2 + p.x) + ba.z; o0.w = dc*(a3 + p.y) + ba.w;
    p = __half22float2(*(__half2*)&sv.z); o1.x = dc*(a4 + p.x) + bb.x; o1.y = dc*(a5 + p.y) + bb.y;
    p = __half22float2(*(__half2*)&sv.w); o1.z = dc*(a6 + p.x) + bb.z; o1.w = dc*(a7 + p.y) + bb.w;

    out4[c * 16 + 2 * j]     = o0;
    out4[c * 16 + 2 * j + 1] = o1;
}

// ---------------------------------------------------------------------------
extern "C" void kernel_launch(void* const* d_in, const int* in_sizes, int n_in,
                              void* d_out, int out_size) {
    const float* x  = nullptr;
    const int*   ei = nullptr;
    const float* Ww = nullptr;
    const float* Wb = nullptr;
    for (int i = 0; i < n_in; i++) {
        int sz = in_sizes[i];
        if (sz == 2 * EE)             ei = (const int*)d_in[i];
        else if (sz == DD * DD)       Ww = (const float*)d_in[i];
        else if (sz == DD)            Wb = (const float*)d_in[i];
        else if (sz == NN * DD && !x) x  = (const float*)d_in[i];
    }
    const int* row = ei;          // sources
    const int* col = ei + EE;     // targets
    float4* out4 = (float4*)d_out;

    deg_kernel          <<<DEG_BLOCKS, 256>>>(col);
    scan_kernel         <<<NB, 1024>>>();
    fused_gemm_bin_kernel<<<GEMM_BLOCKS + BIN_BLOCKS, 256>>>(Ww, x, row, col);
    gather_kernel       <<<(NN * 8 + 255) / 256, 256>>>(Wb, out4);
}